// round 6
// baseline (speedup 1.0000x reference)
#include <cuda_runtime.h>
#include <cuda_bf16.h>

#define NMAX 50000
#define EMAX 1600000
#define D 128
#define NG 64

// ---------------- scratch (static device globals; no allocation) ----------------
__device__ float g_aggp[NMAX * D];
__device__ float g_aggn[NMAX * D];
__device__ float g_x1[NMAX * D];
__device__ float g_x2[NMAX * D];
__device__ int   g_srcs[EMAX];
__device__ float g_cs[EMAX];
__device__ int   g_rowptr[NMAX + 1];
__device__ int   g_cnt[NMAX];
__device__ int   g_cursor[NMAX];
__device__ float g_degp[NMAX], g_degn[NMAX];
__device__ float g_dinvp[NMAX], g_dinvn[NMAX];
__device__ float g_dp2[NMAX], g_dn2[NMAX];
__device__ int   g_gptr[NG + 1];
__device__ int   g_nz_ei;      // nonzero odd-word found in edge_index => int32
__device__ int   g_nz_batch;   // nonzero odd-word found in batch      => int32

// read integer element i from a buffer whose dtype (int32 vs int64) is flagged
__device__ __forceinline__ int idx_at(const void* p, size_t i, int is64) {
    if (is64) return (int)((const long long*)p)[i];
    return ((const int*)p)[i];
}

__device__ __forceinline__ const float* sel_x(int s, const float* xext) {
    return s == 0 ? xext : (s == 1 ? g_x1 : g_x2);
}
__device__ __forceinline__ float* sel_out(int s) {
    return s == 1 ? g_x1 : g_x2;
}

// ---------------- dtype probe ----------------
// Sample odd 32-bit words at indices < element_count (safe for both widths).
// int64 data with values < 2^31 has all-zero odd words; int32 data does not.
__global__ void k_detect(const unsigned* __restrict__ ei, int n_ei,
                         const unsigned* __restrict__ batch, int n_batch) {
    int t = blockIdx.x * blockDim.x + threadIdx.x;
    int total = gridDim.x * blockDim.x;
    int f1 = 0, f2 = 0;
    for (int w = 1 + 2 * t; w < n_ei; w += 2 * total) f1 |= (ei[w] != 0u);
    for (int w = 1 + 2 * t; w < n_batch; w += 2 * total) f2 |= (batch[w] != 0u);
    if (f1) atomicOr(&g_nz_ei, 1);
    if (f2) atomicOr(&g_nz_batch, 1);
}

// ---------------- preprocessing ----------------
__global__ void k_init(int n) {
    int i = blockIdx.x * blockDim.x + threadIdx.x;
    if (i == 0) { g_nz_ei = g_nz_ei; }   // no-op
    if (i < n) {
        g_degp[i] = 1.0f;   // self-loop weight
        g_degn[i] = 1.0f;
        g_cnt[i] = 0;
        g_cursor[i] = 0;
    }
}

__global__ void k_zeroflags() {
    g_nz_ei = 0;
    g_nz_batch = 0;
}

__global__ void k_deg(const void* __restrict__ ei, const float* __restrict__ ew, int e) {
    int i = blockIdx.x * blockDim.x + threadIdx.x;
    if (i >= e) return;
    int is64 = !g_nz_ei;
    int dst = idx_at(ei, (size_t)e + i, is64);
    float w = ew[i];
    atomicAdd(&g_degp[dst], fmaxf(w, 0.0f));
    atomicAdd(&g_degn[dst], fmaxf(-w, 0.0f));
    atomicAdd(&g_cnt[dst], 1);
}

__global__ void k_dinv(int n) {
    int i = blockIdx.x * blockDim.x + threadIdx.x;
    if (i < n) {
        float dp = g_degp[i], dn = g_degn[i];
        g_dinvp[i] = rsqrtf(dp);
        g_dinvn[i] = rsqrtf(dn);
        g_dp2[i] = 1.0f / dp;
        g_dn2[i] = 1.0f / dn;
    }
}

// exclusive scan of g_cnt[0..n) into g_rowptr[0..n]
__global__ void k_scan(int n) {
    __shared__ int sm[1024];
    int t = threadIdx.x;
    int CH = (n + 1023) / 1024;
    int base = t * CH;
    int s = 0;
    for (int i = 0; i < CH; i++) {
        int idx = base + i;
        if (idx < n) s += g_cnt[idx];
    }
    sm[t] = s;
    __syncthreads();
    for (int off = 1; off < 1024; off <<= 1) {
        int v = 0;
        if (t >= off) v = sm[t - off];
        __syncthreads();
        if (t >= off) sm[t] += v;
        __syncthreads();
    }
    int excl = (t == 0) ? 0 : sm[t - 1];
    for (int i = 0; i < CH; i++) {
        int idx = base + i;
        if (idx <= n) {
            g_rowptr[idx] = excl;
            if (idx < n) excl += g_cnt[idx];
        }
    }
}

__global__ void k_scatter(const void* __restrict__ ei, const float* __restrict__ ew, int e) {
    int i = blockIdx.x * blockDim.x + threadIdx.x;
    if (i >= e) return;
    int is64 = !g_nz_ei;
    int src = idx_at(ei, (size_t)i, is64);
    int dst = idx_at(ei, (size_t)e + i, is64);
    float w = ew[i];
    float c;
    if (w >= 0.0f) c = w * g_dinvp[src] * g_dinvp[dst];
    else           c = -((-w) * g_dinvn[src] * g_dinvn[dst]);
    int p = g_rowptr[dst] + atomicAdd(&g_cursor[dst], 1);
    g_srcs[p] = src;
    g_cs[p] = c;
}

// gptr[g] = first index with batch[i] >= g (batch is sorted)
__global__ void k_gptr(const void* __restrict__ batch, int n) {
    int t = threadIdx.x;
    if (t > NG) return;
    int is64 = !g_nz_batch;
    int lo = 0, hi = n;
    while (lo < hi) {
        int mid = (lo + hi) >> 1;
        if (idx_at(batch, (size_t)mid, is64) < t) lo = mid + 1; else hi = mid;
    }
    g_gptr[t] = lo;
}

// ---------------- layer: sparse aggregation (warp per dst node, CSR) ----------------
__global__ void __launch_bounds__(256) k_agg(int xsel, const float* __restrict__ xext, int n) {
    int warp = (blockIdx.x * blockDim.x + threadIdx.x) >> 5;
    if (warp >= n) return;
    const float* __restrict__ x = sel_x(xsel, xext);
    int lane4 = (threadIdx.x & 31) * 4;
    int beg = g_rowptr[warp], end = g_rowptr[warp + 1];
    float4 ap = make_float4(0.f, 0.f, 0.f, 0.f);
    float4 an = make_float4(0.f, 0.f, 0.f, 0.f);
    int i = beg;
    for (; i + 2 <= end; i += 2) {
        int s0 = __ldg(&g_srcs[i]);
        int s1 = __ldg(&g_srcs[i + 1]);
        float c0 = __ldg(&g_cs[i]);
        float c1 = __ldg(&g_cs[i + 1]);
        float4 v0 = *(const float4*)&x[s0 * D + lane4];
        float4 v1 = *(const float4*)&x[s1 * D + lane4];
        if (c0 >= 0.0f) {
            ap.x += c0 * v0.x; ap.y += c0 * v0.y; ap.z += c0 * v0.z; ap.w += c0 * v0.w;
        } else {
            float m = -c0;
            an.x += m * v0.x; an.y += m * v0.y; an.z += m * v0.z; an.w += m * v0.w;
        }
        if (c1 >= 0.0f) {
            ap.x += c1 * v1.x; ap.y += c1 * v1.y; ap.z += c1 * v1.z; ap.w += c1 * v1.w;
        } else {
            float m = -c1;
            an.x += m * v1.x; an.y += m * v1.y; an.z += m * v1.z; an.w += m * v1.w;
        }
    }
    if (i < end) {
        int s0 = __ldg(&g_srcs[i]);
        float c0 = __ldg(&g_cs[i]);
        float4 v0 = *(const float4*)&x[s0 * D + lane4];
        if (c0 >= 0.0f) {
            ap.x += c0 * v0.x; ap.y += c0 * v0.y; ap.z += c0 * v0.z; ap.w += c0 * v0.w;
        } else {
            float m = -c0;
            an.x += m * v0.x; an.y += m * v0.y; an.z += m * v0.z; an.w += m * v0.w;
        }
    }
    *(float4*)&g_aggp[warp * D + lane4] = ap;
    *(float4*)&g_aggn[warp * D + lane4] = an;
}

// ---------------- layer: fused dual GEMM + relu combine ----------------
// x_out[n,:] = relu((aggp[n,:] + dp2[n]*x[n,:]) @ Wp + bp)
//            - relu((aggn[n,:] + dn2[n]*x[n,:]) @ Wn + bn)
#define BM 64
#define BK 8

__device__ __forceinline__ void fma4(float4& acc, float s, const float4& v) {
    acc.x += s * v.x;
    acc.y += s * v.y;
    acc.z += s * v.z;
    acc.w += s * v.w;
}

__global__ void __launch_bounds__(256, 2) k_gemm(
    int xsel, const float* __restrict__ xext,
    const float* __restrict__ Wp, const float* __restrict__ bp,
    const float* __restrict__ Wn, const float* __restrict__ bn,
    int osel, int n)
{
    __shared__ float As[2][BK][BM];
    __shared__ float Ws[2][BK][D];

    const float* __restrict__ x = sel_x(xsel, xext);
    float* __restrict__ xout = sel_out(osel);

    int tid = threadIdx.x;
    int tx = tid & 31;        // 0..31 -> 4 output cols each
    int ty = tid >> 5;        // 0..7  -> 8 output rows each
    int row0 = blockIdx.x * BM;

    float4 accP[8], accN[8];
#pragma unroll
    for (int r = 0; r < 8; r++) {
        accP[r] = make_float4(0.f, 0.f, 0.f, 0.f);
        accN[r] = make_float4(0.f, 0.f, 0.f, 0.f);
    }

    // A-load assignment: threads 0..127 -> pos tile, 128..255 -> neg tile
    int lrow = (tid & 127) >> 1;   // 0..63
    int lk4 = (tid & 1) * 4;       // 0 or 4
    bool isNeg = (tid >= 128);
    int grow = row0 + lrow;
    const float* aggSel = isNeg ? g_aggn : g_aggp;
    const float* d2Sel = isNeg ? g_dn2 : g_dp2;
    float d2 = (grow < n) ? d2Sel[grow] : 0.0f;

    for (int k0 = 0; k0 < D; k0 += BK) {
        // load combined A tile (agg + d2*x)
        float4 av = make_float4(0.f, 0.f, 0.f, 0.f);
        if (grow < n) {
            float4 ag = *(const float4*)&aggSel[grow * D + k0 + lk4];
            float4 xv = *(const float4*)&x[grow * D + k0 + lk4];
            av.x = ag.x + d2 * xv.x;
            av.y = ag.y + d2 * xv.y;
            av.z = ag.z + d2 * xv.z;
            av.w = ag.w + d2 * xv.w;
        }
        int mi = isNeg ? 1 : 0;
        As[mi][lk4 + 0][lrow] = av.x;
        As[mi][lk4 + 1][lrow] = av.y;
        As[mi][lk4 + 2][lrow] = av.z;
        As[mi][lk4 + 3][lrow] = av.w;

        // load W tiles: thread (ty,tx) -> k row ty, cols tx*4..+3
        float4 wp = *(const float4*)&Wp[(k0 + ty) * D + tx * 4];
        float4 wn = *(const float4*)&Wn[(k0 + ty) * D + tx * 4];
        *(float4*)&Ws[0][ty][tx * 4] = wp;
        *(float4*)&Ws[1][ty][tx * 4] = wn;

        __syncthreads();

#pragma unroll
        for (int kk = 0; kk < BK; kk++) {
            float4 wp4 = *(const float4*)&Ws[0][kk][tx * 4];
            float4 wn4 = *(const float4*)&Ws[1][kk][tx * 4];
            float4 aP0 = *(const float4*)&As[0][kk][ty * 8];
            float4 aP1 = *(const float4*)&As[0][kk][ty * 8 + 4];
            float4 aN0 = *(const float4*)&As[1][kk][ty * 8];
            float4 aN1 = *(const float4*)&As[1][kk][ty * 8 + 4];
            fma4(accP[0], aP0.x, wp4); fma4(accP[1], aP0.y, wp4);
            fma4(accP[2], aP0.z, wp4); fma4(accP[3], aP0.w, wp4);
            fma4(accP[4], aP1.x, wp4); fma4(accP[5], aP1.y, wp4);
            fma4(accP[6], aP1.z, wp4); fma4(accP[7], aP1.w, wp4);
            fma4(accN[0], aN0.x, wn4); fma4(accN[1], aN0.y, wn4);
            fma4(accN[2], aN0.z, wn4); fma4(accN[3], aN0.w, wn4);
            fma4(accN[4], aN1.x, wn4); fma4(accN[5], aN1.y, wn4);
            fma4(accN[6], aN1.z, wn4); fma4(accN[7], aN1.w, wn4);
        }
        __syncthreads();
    }

    float4 bp4 = *(const float4*)&bp[tx * 4];
    float4 bn4 = *(const float4*)&bn[tx * 4];
#pragma unroll
    for (int r = 0; r < 8; r++) {
        int gr = row0 + ty * 8 + r;
        if (gr < n) {
            float4 o;
            o.x = fmaxf(accP[r].x + bp4.x, 0.f) - fmaxf(accN[r].x + bn4.x, 0.f);
            o.y = fmaxf(accP[r].y + bp4.y, 0.f) - fmaxf(accN[r].y + bn4.y, 0.f);
            o.z = fmaxf(accP[r].z + bp4.z, 0.f) - fmaxf(accN[r].z + bn4.z, 0.f);
            o.w = fmaxf(accP[r].w + bp4.w, 0.f) - fmaxf(accN[r].w + bn4.w, 0.f);
            *(float4*)&xout[gr * D + tx * 4] = o;
        }
    }
}

// ---------------- pooling + layernorm ----------------
__global__ void k_pool_ln(int xsel, const float* __restrict__ xext,
                          const float* __restrict__ gamma, const float* __restrict__ beta,
                          float* __restrict__ out)
{
    const float* __restrict__ x = sel_x(xsel, xext);
    int g = blockIdx.x;
    int c = threadIdx.x;   // 0..127
    int b = g_gptr[g], e = g_gptr[g + 1];
    float s = 0.f;
    for (int i = b; i < e; i++) s += x[i * D + c];
    float cnt = fmaxf((float)(e - b), 1.0f);
    float p = s / cnt;

    // block reduce sum(p) and sum(p*p) over 128 threads
    __shared__ float red1[4], red2[4];
    float v1 = p, v2 = p * p;
#pragma unroll
    for (int off = 16; off > 0; off >>= 1) {
        v1 += __shfl_xor_sync(0xffffffff, v1, off);
        v2 += __shfl_xor_sync(0xffffffff, v2, off);
    }
    int w = c >> 5, l = c & 31;
    if (l == 0) { red1[w] = v1; red2[w] = v2; }
    __syncthreads();
    float s1 = red1[0] + red1[1] + red1[2] + red1[3];
    float s2 = red2[0] + red2[1] + red2[2] + red2[3];
    float mu = s1 * (1.0f / D);
    float var = s2 * (1.0f / D) - mu * mu;
    float inv = rsqrtf(var + 1e-5f);
    out[g * D + c] = (p - mu) * inv * gamma[c] + beta[c];
}

// ---------------- launch ----------------
extern "C" void kernel_launch(void* const* d_in, const int* in_sizes, int n_in,
                              void* d_out, int out_size) {
    const float* x = (const float*)d_in[0];
    const void* ei = d_in[1];
    const float* ew = (const float*)d_in[2];
    const void* batch = d_in[3];
    const float* W_pos = (const float*)d_in[4];
    const float* b_pos = (const float*)d_in[5];
    const float* W_neg = (const float*)d_in[6];
    const float* b_neg = (const float*)d_in[7];
    const float* gamma = (const float*)d_in[8];
    const float* beta = (const float*)d_in[9];

    int N = in_sizes[0] / D;
    int E = in_sizes[1] / 2;
    int NB = in_sizes[3];   // batch element count

    int nb = (N + 255) / 256;
    int eb = (E + 255) / 256;

    k_zeroflags<<<1, 1>>>();
    k_detect<<<32, 256>>>((const unsigned*)ei, 2 * E, (const unsigned*)batch, NB);
    k_init<<<nb, 256>>>(N);
    k_deg<<<eb, 256>>>(ei, ew, E);
    k_dinv<<<nb, 256>>>(N);
    k_scan<<<1, 1024>>>(N);
    k_scatter<<<eb, 256>>>(ei, ew, E);
    k_gptr<<<1, 128>>>(batch, N);

    int aggBlocks = (N * 32 + 255) / 256;
    int gemmBlocks = (N + BM - 1) / BM;

    // layer 0: x(ext) -> g_x1
    k_agg<<<aggBlocks, 256>>>(0, x, N);
    k_gemm<<<gemmBlocks, 256>>>(0, x, W_pos, b_pos, W_neg, b_neg, 1, N);
    // layer 1: g_x1 -> g_x2
    k_agg<<<aggBlocks, 256>>>(1, x, N);
    k_gemm<<<gemmBlocks, 256>>>(1, x, W_pos + D * D, b_pos + D, W_neg + D * D, b_neg + D, 2, N);
    // layer 2: g_x2 -> g_x1
    k_agg<<<aggBlocks, 256>>>(2, x, N);
    k_gemm<<<gemmBlocks, 256>>>(2, x, W_pos + 2 * D * D, b_pos + 2 * D, W_neg + 2 * D * D, b_neg + 2 * D, 1, N);

    k_pool_ln<<<NG, 128>>>(1, x, gamma, beta, (float*)d_out);
}